// round 15
// baseline (speedup 1.0000x reference)
// R15: revert R13 (LDG-through-L1 lesson), base = R12 (best, 264.7us).
// Change: 4 warps x 64x64 warp tiles (128 thr/CTA) -> fragment wavefronts
// -33% (384->256 per iter). Same validated pipeline/loader/80B rows/acc order.
#include <cuda_runtime.h>
#include <cuda_bf16.h>
#include <cstdint>

#define T_TOK 1024
#define H_DIM 1024
#define NE 32
#define TOPK 4
#define F_DIM 1024
#define TWO_F 2048
#define LIMIT 7.0f
#define ALPHA 1.702f
#define EPS 1e-5f

#define BM 128
#define BN 128
#define BK 32
#define STG 10240          // bytes per stage per array (128 rows * 80B)

// ------------------- scratch -------------------
__device__ __nv_bfloat16 g_tnorm_h[T_TOK * H_DIM];
__device__ int   g_counts[NE];
__device__ int   g_bases[NE];
__device__ int   g_expert_ids[T_TOK * TOPK];
__device__ float g_weights[T_TOK * TOPK];
__device__ int   g_slot_token[T_TOK * TOPK];
__device__ float g_slot_weight[T_TOK * TOPK];
__device__ int   g_token_slot[T_TOK * TOPK];
__device__ __nv_bfloat16 g_act_h[(size_t)T_TOK * TOPK * F_DIM];
__device__ float g_y[(size_t)T_TOK * TOPK * H_DIM];

// ------------------- helpers -------------------
__device__ __forceinline__ void mma_bf16(float (&d)[4], const uint32_t (&a)[4],
                                         uint32_t b0, uint32_t b1) {
    asm volatile(
        "mma.sync.aligned.m16n8k16.row.col.f32.bf16.bf16.f32 "
        "{%0,%1,%2,%3}, {%4,%5,%6,%7}, {%8,%9}, {%0,%1,%2,%3};\n"
        : "+f"(d[0]), "+f"(d[1]), "+f"(d[2]), "+f"(d[3])
        : "r"(a[0]), "r"(a[1]), "r"(a[2]), "r"(a[3]), "r"(b0), "r"(b1));
}
__device__ __forceinline__ void ldsm4(uint32_t (&r)[4], uint32_t addr) {
    asm volatile("ldmatrix.sync.aligned.m8n8.x4.shared.b16 {%0,%1,%2,%3}, [%4];"
                 : "=r"(r[0]), "=r"(r[1]), "=r"(r[2]), "=r"(r[3]) : "r"(addr));
}
__device__ __forceinline__ uint32_t packbf(float lo, float hi) {
    uint32_t r;
    asm("cvt.rn.bf16x2.f32 %0, %1, %2;" : "=r"(r) : "f"(hi), "f"(lo));
    return r;
}
__device__ __forceinline__ void cp16(uint32_t dst, const void* src, uint32_t sz) {
    asm volatile("cp.async.ca.shared.global [%0], [%1], 16, %2;\n"
                 ::"r"(dst), "l"(src), "r"(sz));
}
__device__ __forceinline__ void cp_commit() { asm volatile("cp.async.commit_group;\n"); }
__device__ __forceinline__ void cp_wait0() { asm volatile("cp.async.wait_group 0;\n"); }

// load + pack one full B row-chunk of k32 (8 LDG.128 -> 4 packed uint4)
__device__ __forceinline__ void ldpackB(uint4 (&o)[4], const float* p, int k0) {
#pragma unroll
    for (int j = 0; j < 4; j++) {
        float4 x0 = *(const float4*)(p + k0 + j * 8);
        float4 x1 = *(const float4*)(p + k0 + j * 8 + 4);
        o[j].x = packbf(x0.x, x0.y);
        o[j].y = packbf(x0.z, x0.w);
        o[j].z = packbf(x1.x, x1.y);
        o[j].w = packbf(x1.z, x1.w);
    }
}

// ------------------- kernel 0 -------------------
__global__ void k_zero() {
    if (threadIdx.x < NE) g_counts[threadIdx.x] = 0;
}

// ------------------- kernel 1: rmsnorm + gate + top4 + softmax ----------------
__global__ void k_gate(const float* __restrict__ x, const float* __restrict__ scale,
                       const float* __restrict__ gw, const float* __restrict__ gb) {
    int t = blockIdx.x;
    int tid = threadIdx.x;
    __shared__ float sh[H_DIM];
    __shared__ float red[8];
    __shared__ float logits[NE];
    const float* xr = x + (size_t)t * H_DIM;

    float ss = 0.f;
    for (int i = tid; i < H_DIM; i += 256) { float v = xr[i]; ss += v * v; }
    for (int o = 16; o; o >>= 1) ss += __shfl_xor_sync(~0u, ss, o);
    int warp = tid >> 5, lane = tid & 31;
    if (!lane) red[warp] = ss;
    __syncthreads();
    if (tid < 8) {
        float s = red[tid];
        for (int o = 4; o; o >>= 1) s += __shfl_xor_sync(0xffu, s, o);
        if (!tid) red[0] = s;
    }
    __syncthreads();
    float inv = rsqrtf(red[0] * (1.0f / H_DIM) + EPS);
    for (int i = tid; i < H_DIM; i += 256) {
        float v = xr[i] * inv * scale[i];
        sh[i] = v;
        g_tnorm_h[(size_t)t * H_DIM + i] = __float2bfloat16_rn(v);
    }
    __syncthreads();
    for (int e = warp; e < NE; e += 8) {
        const float* w = gw + (size_t)e * H_DIM;
        float s = 0.f;
        for (int i = lane; i < H_DIM; i += 32) s += sh[i] * w[i];
        for (int o = 16; o; o >>= 1) s += __shfl_xor_sync(~0u, s, o);
        if (!lane) logits[e] = s + gb[e];
    }
    __syncthreads();
    if (tid == 0) {
        unsigned used = 0;
        float v[TOPK]; int ix[TOPK];
        for (int k = 0; k < TOPK; k++) {
            float best = -3.4e38f; int bi = 0;
            for (int e2 = 0; e2 < NE; e2++)
                if (!((used >> e2) & 1u) && logits[e2] > best) { best = logits[e2]; bi = e2; }
            used |= 1u << bi; v[k] = best; ix[k] = bi;
        }
        float mx = v[0], sum = 0.f, w4[TOPK];
        for (int k = 0; k < TOPK; k++) { w4[k] = __expf(v[k] - mx); sum += w4[k]; }
        float rs = 1.f / sum;
        for (int k = 0; k < TOPK; k++) {
            g_expert_ids[t * TOPK + k] = ix[k];
            g_weights[t * TOPK + k] = w4[k] * rs;
            atomicAdd(&g_counts[ix[k]], 1);
        }
    }
}

// ------------------- kernel 2: deterministic scatter --------------------------
__global__ void k_scatter() {
    int e = threadIdx.x >> 5;
    int lane = threadIdx.x & 31;
    int base = 0;
    for (int i = 0; i < e; i++) base += g_counts[i];
    if (!lane) g_bases[e] = base;
    int running = 0;
    for (int j0 = 0; j0 < T_TOK * TOPK; j0 += 32) {
        int j = j0 + lane;
        int ee = g_expert_ids[j];
        unsigned m = __ballot_sync(~0u, ee == e);
        if (ee == e) {
            int slot = base + running + __popc(m & ((1u << lane) - 1u));
            g_slot_token[slot] = j >> 2;
            g_slot_weight[slot] = g_weights[j];
            g_token_slot[j] = slot;
        }
        running += __popc(m);
    }
}

// ------------------- kernel 3/4: bf16 HMMA GEMM, 4 warps x 64x64 --------------
// IS_G1=1: act_h[slot,f] = bf16(w_slot * swiglu(tnorm_h[token] @ w1[e]^T + b1[e]))
// IS_G1=0: y[slot,h]     = act_h[slot,:] @ w2[e]^T
template <int IS_G1>
__global__ __launch_bounds__(128, 2) void k_gemm(const float* __restrict__ W,
                                                 const float* __restrict__ bias) {
    const int Kd = 1024;
    const int Nd = IS_G1 ? TWO_F : H_DIM;
    const int e = blockIdx.z;
    const int cnt = g_counts[e];
    const int m0 = blockIdx.y * BM;
    if (m0 >= cnt) return;
    const int base = g_bases[e];
    const int n0 = blockIdx.x * BN;

    __shared__ __align__(16) __nv_bfloat16 As[2][128 * 40];  // 80B rows
    __shared__ __align__(16) __nv_bfloat16 Bs[2][128 * 40];

    const int tid = threadIdx.x;           // 0..127
    const int warp = tid >> 5, lane = tid & 31;
    const int g = lane >> 2, tg = lane & 3;
    const int wm = (warp & 1) * 64;        // 2 warp-rows of 64
    const int wn = (warp >> 1) * 64;       // 2 warp-cols of 64

    // ---- loader: one row per thread ----
    const __nv_bfloat16* asrc;
    uint32_t asz = 0;
    if (m0 + tid < cnt) {
        int s = base + m0 + tid;
        asrc = IS_G1 ? (g_tnorm_h + (size_t)g_slot_token[s] * H_DIM)
                     : (g_act_h + (size_t)s * F_DIM);
        asz = 16;
    } else {
        asrc = g_tnorm_h;
    }
    const uint32_t aDst = (uint32_t)__cvta_generic_to_shared(As) + (uint32_t)(tid * 80);
    const float* bsrc = W + (size_t)e * Nd * Kd + (size_t)(n0 + tid) * Kd;
    const uint32_t bDst = (uint32_t)__cvta_generic_to_shared(Bs) + (uint32_t)(tid * 80);

    // ---- ldmatrix per-lane fragment bases (stage 0) ----
    const int q = lane >> 3, qr = lane & 7;
    const uint32_t aFrag = (uint32_t)__cvta_generic_to_shared(As)
        + (uint32_t)((wm + (q & 1) * 8 + qr) * 80 + (q >> 1) * 16);
    const uint32_t bFrag = (uint32_t)__cvta_generic_to_shared(Bs)
        + (uint32_t)((wn + (q >> 1) * 8 + qr) * 80 + (q & 1) * 16);

    float acc[4][8][4];
#pragma unroll
    for (int mi = 0; mi < 4; mi++)
#pragma unroll
        for (int ni = 0; ni < 8; ni++)
#pragma unroll
            for (int z = 0; z < 4; z++) acc[mi][ni][z] = 0.f;

    // ---- prologue ----
#pragma unroll
    for (int j = 0; j < 4; j++) cp16(aDst + j * 16, asrc + j * 8, asz);
    cp_commit();
    uint4 Bst[4];
    ldpackB(Bst, bsrc, 0);

    const int NIT = Kd / BK;  // 32
#pragma unroll 1
    for (int it = 0; it < NIT; it++) {
        const uint32_t s = (uint32_t)(it & 1);
        // STS staged B into stage s
#pragma unroll
        for (int j = 0; j < 4; j++)
            asm volatile("st.shared.v4.b32 [%0], {%1,%2,%3,%4};"
                         ::"r"(bDst + s * STG + j * 16),
                           "r"(Bst[j].x), "r"(Bst[j].y), "r"(Bst[j].z), "r"(Bst[j].w));
        cp_wait0();          // A stage s complete
        __syncthreads();
        if (it + 1 < NIT) {  // prefetch next (overlapped with MMAs below)
            const int k1 = (it + 1) * BK;
#pragma unroll
            for (int j = 0; j < 4; j++)
                cp16(aDst + (s ^ 1) * STG + j * 16, asrc + k1 + j * 8, asz);
            cp_commit();
            ldpackB(Bst, bsrc, k1);
        }
        const uint32_t aS = aFrag + s * STG;
        const uint32_t bS = bFrag + s * STG;
#pragma unroll
        for (int kk = 0; kk < 2; kk++) {
            uint32_t a[4][4], bq[4][4];
#pragma unroll
            for (int mi = 0; mi < 4; mi++)
                ldsm4(a[mi], aS + (uint32_t)(mi * 16 * 80 + kk * 32));
#pragma unroll
            for (int p = 0; p < 4; p++)
                ldsm4(bq[p], bS + (uint32_t)(p * 16 * 80 + kk * 32));
#pragma unroll
            for (int mi = 0; mi < 4; mi++) {
#pragma unroll
                for (int p = 0; p < 4; p++) {
                    mma_bf16(acc[mi][2 * p + 0], a[mi], bq[p][0], bq[p][1]);
                    mma_bf16(acc[mi][2 * p + 1], a[mi], bq[p][2], bq[p][3]);
                }
            }
        }
    }

    // ---- epilogue (same formulas; ni now 0..7, wm/wn 64-wide) ----
#pragma unroll
    for (int mi = 0; mi < 4; mi++) {
#pragma unroll
        for (int h2 = 0; h2 < 2; h2++) {
            int r = m0 + wm + mi * 16 + g + h2 * 8;
            if (r >= cnt) continue;
            int slot = base + r;
            float wsl = IS_G1 ? g_slot_weight[slot] : 0.f;
#pragma unroll
            for (int ni = 0; ni < 8; ni++) {
                int ceven = n0 + wn + ni * 8 + 2 * tg;
                float v0 = acc[mi][ni][h2 * 2 + 0];
                float v1 = acc[mi][ni][h2 * 2 + 1];
                if (IS_G1) {
                    const float2 bb = *(const float2*)(bias + (size_t)e * TWO_F + ceven);
                    float glu = fminf(v0 + bb.x, LIMIT);
                    float lin = fminf(fmaxf(v1 + bb.y, -LIMIT), LIMIT);
                    float act = glu * (1.f / (1.f + __expf(-ALPHA * glu))) * (lin + 1.f);
                    g_act_h[(size_t)slot * F_DIM + (ceven >> 1)] =
                        __float2bfloat16_rn(wsl * act);
                } else {
                    *(float2*)(g_y + (size_t)slot * H_DIM + ceven) = make_float2(v0, v1);
                }
            }
        }
    }
}

// ------------------- kernel 5: combine + residual + b2 -------------------
__global__ void k_combine(const float* __restrict__ x, const float* __restrict__ b2,
                          float* __restrict__ out) {
    int t = blockIdx.x, tid = threadIdx.x;
    int s0 = g_token_slot[t * 4 + 0], s1 = g_token_slot[t * 4 + 1];
    int s2 = g_token_slot[t * 4 + 2], s3 = g_token_slot[t * 4 + 3];
    int e0 = g_expert_ids[t * 4 + 0], e1 = g_expert_ids[t * 4 + 1];
    int e2 = g_expert_ids[t * 4 + 2], e3 = g_expert_ids[t * 4 + 3];
    float w0 = g_weights[t * 4 + 0], w1v = g_weights[t * 4 + 1];
    float w2v = g_weights[t * 4 + 2], w3 = g_weights[t * 4 + 3];
    for (int i = tid; i < H_DIM; i += 256) {
        float v = x[(size_t)t * H_DIM + i];
        v += g_y[(size_t)s0 * H_DIM + i] + w0 * b2[(size_t)e0 * H_DIM + i];
        v += g_y[(size_t)s1 * H_DIM + i] + w1v * b2[(size_t)e1 * H_DIM + i];
        v += g_y[(size_t)s2 * H_DIM + i] + w2v * b2[(size_t)e2 * H_DIM + i];
        v += g_y[(size_t)s3 * H_DIM + i] + w3 * b2[(size_t)e3 * H_DIM + i];
        out[(size_t)t * H_DIM + i] = v;
    }
}

// ------------------- launcher -------------------
extern "C" void kernel_launch(void* const* d_in, const int* in_sizes, int n_in,
                              void* d_out, int out_size) {
    const float* x = (const float*)d_in[0];
    const float* norm_scale = (const float*)d_in[1];
    const float* gate_w = (const float*)d_in[2];
    const float* gate_b = (const float*)d_in[3];
    const float* w1 = (const float*)d_in[4];
    const float* b1 = (const float*)d_in[5];
    const float* w2 = (const float*)d_in[6];
    const float* b2 = (const float*)d_in[7];
    float* out = (float*)d_out;

    k_zero<<<1, 32>>>();
    k_gate<<<T_TOK, 256>>>(x, norm_scale, gate_w, gate_b);
    k_scatter<<<1, 1024>>>();
    dim3 grid1(TWO_F / BN, T_TOK / BM, NE); // (16, 8, 32)
    k_gemm<1><<<grid1, 128>>>(w1, b1);
    dim3 grid2(H_DIM / BN, T_TOK / BM, NE); // (8, 8, 32)
    k_gemm<0><<<grid2, 128>>>(w2, nullptr);
    k_combine<<<T_TOK, 256>>>(x, b2, out);
}